// round 9
// baseline (speedup 1.0000x reference)
#include <cuda_runtime.h>
#include <cuda_fp16.h>
#include <math.h>
#include <stdint.h>

// ---------------- problem constants ----------------
#define BB 64
#define SQ 64
#define SD 512
#define KH 4
#define DD 128
#define NCOLS (BB + KH)
#define INV_T 50.0f

#define NSETS 4               // doc sets per block (share one A tile)
#define NCHT (NSETS * 4)      // 16 total 128-doc chunks per block
#define RST 272               // smem row stride bytes: 128 fp16 + 8 pad
#define BSTG (128 * RST)      // 34816 bytes per B stage

// smem layout (bytes)
#define SM_A 0
#define SM_B 34816            // 2 stages
#define SM_REDP 104448        // uint32[128][4]
#define SM_WIDX 106496        // int[128]
#define SM_EXSC 107008        // float[128]
#define SMEM_TOTAL 107520     // x2 CTAs = 215040 <= 227KB

// fp16 copies of inputs (static device scratch; allocation-free)
__device__ __half Qh[BB * SQ * DD];
__device__ __half Ph[BB * SD * DD];
__device__ __half HNh[BB * KH * SD * DD];
__device__ float g_scores[BB][NCOLS];

__device__ __forceinline__ uint32_t smem_u32(const void* p) {
    uint32_t a;
    asm("{ .reg .u64 t; cvta.to.shared.u64 t, %1; cvt.u32.u64 %0, t; }" : "=r"(a) : "l"(p));
    return a;
}

#define CP_ASYNC16(dst, src) \
    asm volatile("cp.async.cg.shared.global [%0], [%1], 16;" :: "r"((uint32_t)(dst)), "l"(src))
#define CP_COMMIT asm volatile("cp.async.commit_group;" ::: "memory")
#define CP_WAIT(n) asm volatile("cp.async.wait_group %0;" :: "n"(n) : "memory")

#define LDSM4(r, a) \
    asm volatile("ldmatrix.sync.aligned.m8n8.x4.shared.b16 {%0,%1,%2,%3}, [%4];" \
        : "=r"((r)[0]), "=r"((r)[1]), "=r"((r)[2]), "=r"((r)[3]) : "r"(a))

#define MMA16816(c, a, b0, b1) \
    asm volatile("mma.sync.aligned.m16n8k16.row.col.f32.f16.f16.f32 " \
        "{%0,%1,%2,%3}, {%4,%5,%6,%7}, {%8,%9}, {%0,%1,%2,%3};" \
        : "+f"((c)[0]), "+f"((c)[1]), "+f"((c)[2]), "+f"((c)[3]) \
        : "r"((a)[0]), "r"((a)[1]), "r"((a)[2]), "r"((a)[3]), "r"(b0), "r"(b1))

// order-preserving float->uint, low 9 bits replaced by doc index
__device__ __forceinline__ uint32_t packmax(float v, uint32_t idx) {
    uint32_t u = __float_as_uint(v);
    u = u ^ (((uint32_t)((int)u >> 31)) | 0x80000000u);
    return (u & 0xFFFFFE00u) | idx;
}

// ---------------- fused fp32 -> fp16 preconvert ----------------
#define N4_Q (BB * SQ * DD / 4)
#define N4_P (BB * SD * DD / 4)
#define N4_HN (BB * KH * SD * DD / 4)
#define N4_TOT (N4_Q + N4_P + N4_HN)

__global__ void cvt_all_kernel(const float4* __restrict__ Q,
                               const float4* __restrict__ P,
                               const float4* __restrict__ HN)
{
    const int i = blockIdx.x * blockDim.x + threadIdx.x;
    if (i >= N4_TOT) return;
    const float4* src; uint2* dst; int j;
    if (i < N4_Q)               { src = Q;  dst = (uint2*)Qh;  j = i; }
    else if (i < N4_Q + N4_P)   { src = P;  dst = (uint2*)Ph;  j = i - N4_Q; }
    else                        { src = HN; dst = (uint2*)HNh; j = i - N4_Q - N4_P; }
    const float4 f = src[j];
    union { __half h[4]; uint2 u; } p;
    p.h[0] = __float2half_rn(f.x);
    p.h[1] = __float2half_rn(f.y);
    p.h[2] = __float2half_rn(f.z);
    p.h[3] = __float2half_rn(f.w);
    dst[j] = p.u;
}

__device__ __forceinline__ void load_B_chunk(uint32_t dst_base, const __half* src, int tid)
{
#pragma unroll
    for (int j = 0; j < 8; ++j) {
        const int it = tid + j * 256;
        const int row = it >> 4, ci = it & 15;
        CP_ASYNC16(dst_base + row * RST + ci * 16, src + row * DD + ci * 8);
    }
}

// ---------------- main kernel ----------------
__global__ __launch_bounds__(256, 2) void maxsim_kernel(
    const float* __restrict__ Q,
    const float* __restrict__ P,
    const float* __restrict__ HN)
{
    extern __shared__ char sm[];
    const uint32_t smb = smem_u32(sm);
    const int tid = threadIdx.x;
    const int wid = tid >> 5;
    const int lid = tid & 31;

    // ---- block -> work mapping: 512 in-batch + 64 HN blocks, 4 sets each ----
    const __half* aH; const __half* bAllH;
    const float* aF; const float* bAllF;
    int qrow0, outcol0, validM;
    const int bidx = blockIdx.x;
    if (bidx < 512) {
        const int mt = bidx >> 4, sg = bidx & 15;
        aH = Qh + (size_t)mt * 128 * DD;  aF = Q + (size_t)mt * 128 * DD;
        const int bp0 = sg * 4;
        bAllH = Ph + (size_t)bp0 * SD * DD;
        bAllF = P + (size_t)bp0 * SD * DD;
        qrow0 = mt * 2; outcol0 = bp0; validM = 128;
    } else {
        const int b = bidx - 512;
        aH = Qh + (size_t)b * SQ * DD;    aF = Q + (size_t)b * SQ * DD;
        bAllH = HNh + (size_t)b * KH * SD * DD;
        bAllF = HN + (size_t)b * KH * SD * DD;
        qrow0 = b; outcol0 = BB; validM = 64;
    }

    // ---- prologue: A (group 0) + chunks 0,1 (groups 1,2) ----
#pragma unroll
    for (int j = 0; j < 8; ++j) {
        const int it = tid + j * 256;
        const int row = it >> 4, ci = it & 15;
        if (row < validM)
            CP_ASYNC16(smb + SM_A + row * RST + ci * 16, aH + row * DD + ci * 8);
    }
    if (validM == 64) {  // zero upper A rows for HN blocks
        for (int j = tid; j < 1088; j += 256) {
            const int row = 64 + j / 17, ci = j % 17;
            *(uint4*)(sm + SM_A + row * RST + ci * 16) = make_uint4(0, 0, 0, 0);
        }
    }
    CP_COMMIT;
    load_B_chunk(smb + SM_B, bAllH, tid);
    CP_COMMIT;
    load_B_chunk(smb + SM_B + BSTG, bAllH + (size_t)128 * DD, tid);
    CP_COMMIT;

    // ---- fragment addressing ----
    const int wm = wid >> 2, wn = wid & 3;
    const int m0 = wm * 64, n0 = wn * 32;
    const int a_r = (lid & 7) + ((lid >> 3) & 1) * 8;
    const uint32_t a_c = ((lid >> 4) & 1) * 16;
    const uint32_t aBase = smb + SM_A + (uint32_t)((m0 + a_r) * RST) + a_c;
    const int b_r = ((lid >> 4) & 1) * 8 + (lid & 7);
    const uint32_t b_c = ((lid >> 3) & 1) * 16;
    uint32_t bOffH[2];
#pragma unroll
    for (int h = 0; h < 2; ++h)
        bOffH[h] = (uint32_t)((n0 + h * 16 + b_r) * RST) + b_c;

    uint32_t* redp = (uint32_t*)(sm + SM_REDP);
    int* widx = (int*)(sm + SM_WIDX);
    float* exsc = (float*)(sm + SM_EXSC);

    // ================= set loop =================
#pragma unroll 1
    for (int su = 0; su < NSETS; ++su) {
        uint32_t rmp[4][2];
#pragma unroll
        for (int mt = 0; mt < 4; ++mt) { rmp[mt][0] = 0u; rmp[mt][1] = 0u; }

#pragma unroll 1
        for (int ch = 0; ch < 4; ++ch) {
            const int g = su * 4 + ch;
            if (g == NCHT - 1) { CP_WAIT(0); } else { CP_WAIT(1); }
            __syncthreads();

            const uint32_t bb = smb + SM_B + (uint32_t)(g & 1) * BSTG;

            // two 16-column halves (keeps accumulator at 32 regs)
#pragma unroll
            for (int half = 0; half < 2; ++half) {
                float acc[4][2][4];
#pragma unroll
                for (int mt = 0; mt < 4; ++mt)
#pragma unroll
                    for (int n8 = 0; n8 < 2; ++n8)
#pragma unroll
                        for (int i = 0; i < 4; ++i) acc[mt][n8][i] = 0.f;

#pragma unroll
                for (int kk = 0; kk < 8; ++kk) {
                    const uint32_t ko = kk * 32;
                    uint32_t af[4][4], bf[4];
                    LDSM4(af[0], aBase + ko);
                    LDSM4(af[1], aBase + 16 * RST + ko);
                    LDSM4(af[2], aBase + 32 * RST + ko);
                    LDSM4(af[3], aBase + 48 * RST + ko);
                    LDSM4(bf, bb + bOffH[half] + ko);
#pragma unroll
                    for (int mt = 0; mt < 4; ++mt) {
                        MMA16816(acc[mt][0], af[mt], bf[0], bf[1]);
                        MMA16816(acc[mt][1], af[mt], bf[2], bf[3]);
                    }
                }

                // fold: col = ch*128 + n0 + half*16 + n8*8 + 2*(lid&3) + j
                const uint32_t base = (uint32_t)(ch * 128 + n0 + half * 16 + 2 * (lid & 3));
#pragma unroll
                for (int mt = 0; mt < 4; ++mt)
#pragma unroll
                    for (int n8 = 0; n8 < 2; ++n8)
#pragma unroll
                        for (int h = 0; h < 2; ++h)
#pragma unroll
                            for (int j = 0; j < 2; ++j) {
                                const uint32_t pk =
                                    packmax(acc[mt][n8][h * 2 + j], base + n8 * 8 + j);
                                rmp[mt][h] = (pk > rmp[mt][h]) ? pk : rmp[mt][h];
                            }
            }
            __syncthreads();

            // stream next chunk (possibly next set's) into the freed stage
            const int gn = g + 2;
            if (gn < NCHT) {
                load_B_chunk(smb + SM_B + (uint32_t)(gn & 1) * BSTG,
                             bAllH + (size_t)gn * 128 * DD, tid);
                CP_COMMIT;
            }
        }

        // ---- per-set epilogue ----
        const float* bF = bAllF + (size_t)su * SD * DD;
        const int outcol = outcol0 + su;

#pragma unroll
        for (int mt = 0; mt < 4; ++mt)
#pragma unroll
            for (int h = 0; h < 2; ++h) {
                uint32_t v = rmp[mt][h];
#pragma unroll
                for (int o = 1; o <= 2; o <<= 1) {
                    const uint32_t ov = __shfl_xor_sync(0xffffffffu, v, o);
                    v = (ov > v) ? ov : v;
                }
                if ((lid & 3) == 0)
                    redp[(m0 + mt * 16 + h * 8 + (lid >> 2)) * 4 + wn] = v;
            }
        __syncthreads();

        if (tid < 128) {
            uint32_t best = redp[tid * 4];
#pragma unroll
            for (int w = 1; w < 4; ++w) {
                const uint32_t v = redp[tid * 4 + w];
                best = (v > best) ? v : best;
            }
            widx[tid] = (int)(best & 0x1FFu);
        }
        __syncthreads();

        // exact fp32 rescore of winners (2 threads per row)
        {
            const int r = tid >> 1, hf = tid & 1;
            const int rr = (r < validM) ? r : 0;
            const float* qp = aF + (size_t)rr * DD + hf * 64;
            const float* dp = bF + (size_t)widx[rr] * DD + hf * 64;
            float a0 = 0.f, a1 = 0.f, a2 = 0.f, a3 = 0.f;
#pragma unroll
            for (int j = 0; j < 16; ++j) {
                const float4 qv = __ldg((const float4*)(qp + j * 4));
                const float4 dv = __ldg((const float4*)(dp + j * 4));
                a0 = fmaf(qv.x, dv.x, a0);
                a1 = fmaf(qv.y, dv.y, a1);
                a2 = fmaf(qv.z, dv.z, a2);
                a3 = fmaf(qv.w, dv.w, a3);
            }
            float s = (a0 + a1) + (a2 + a3);
            s += __shfl_xor_sync(0xffffffffu, s, 1);
            if (hf == 0 && r < validM) exsc[r] = s;
        }
        __syncthreads();

        if (wid < (validM >> 6)) {
            float s = exsc[wid * 64 + lid] + exsc[wid * 64 + 32 + lid];
#pragma unroll
            for (int o = 16; o > 0; o >>= 1) s += __shfl_down_sync(0xffffffffu, s, o);
            if (lid == 0) g_scores[qrow0 + wid][outcol] = s;
        }
        __syncthreads();
    }
}

// ---------------- loss kernel ----------------
__global__ void loss_kernel(float* __restrict__ out)
{
    __shared__ float red[BB];
    const int q = threadIdx.x >> 1, part = threadIdx.x & 1;
    const float* row = &g_scores[q][0];
    const float pos = row[q];

    float m = -INFINITY;
    for (int j = part * 34; j < part * 34 + 34; ++j) m = fmaxf(m, row[j]);
    m = fmaxf(m, __shfl_xor_sync(0xffffffffu, m, 1));
    m = fmaxf(m, pos);

    float sum = (part == 0) ? expf((pos - m) * INV_T) : 0.f;
    for (int j = part * 34; j < part * 34 + 34; ++j) sum += expf((row[j] - m) * INV_T);
    sum += __shfl_xor_sync(0xffffffffu, sum, 1);

    if (part == 0) red[q] = m * INV_T + logf(sum) - pos * INV_T;
    __syncthreads();

    if (threadIdx.x < 32) {
        float s = red[threadIdx.x] + red[threadIdx.x + 32];
#pragma unroll
        for (int o = 16; o > 0; o >>= 1) s += __shfl_down_sync(0xffffffffu, s, o);
        if (threadIdx.x == 0) out[0] = s / (float)BB;
    }
}

extern "C" void kernel_launch(void* const* d_in, const int* in_sizes, int n_in,
                              void* d_out, int out_size)
{
    const float* Q  = (const float*)d_in[0];
    const float* P  = (const float*)d_in[1];
    const float* HN = (const float*)d_in[2];
    (void)in_sizes; (void)n_in; (void)out_size;

    static bool attr_set = false;
    if (!attr_set) {
        cudaFuncSetAttribute(maxsim_kernel,
                             cudaFuncAttributeMaxDynamicSharedMemorySize, SMEM_TOTAL);
        attr_set = true;
    }

    cvt_all_kernel<<<(N4_TOT + 255) / 256, 256>>>(
        (const float4*)Q, (const float4*)P, (const float4*)HN);
    maxsim_kernel<<<512 + BB, 256, SMEM_TOTAL>>>(Q, P, HN);
    loss_kernel<<<1, 128>>>((float*)d_out);
}

// round 10
// speedup vs baseline: 2.7091x; 2.7091x over previous
#include <cuda_runtime.h>
#include <math.h>
#include <stdint.h>

// ---------------- problem constants ----------------
#define BB 64
#define SQ 64
#define SD 512
#define KH 4
#define DD 128
#define NCOLS (BB + KH)
#define INV_T 50.0f
#define SCALE_I8 25.0f

#define NCHUNK 4              // 512 docs / 128 per chunk
#define RST 144               // smem row stride bytes: 128 int8 + 16 pad
#define BSTG (128 * RST)      // 18432 bytes per B stage

// smem layout (bytes)
#define SM_A 0                // 128 x 144 = 18432
#define SM_B 18432            // 2 stages x 18432
#define SM_REDP 55296         // uint32[128][4]
#define SM_WIDX 57344         // int[128]
#define SM_EXSC 57856         // float[128]
#define SMEM_TOTAL 58368

// int8 copies of inputs (static device scratch; allocation-free)
__device__ int8_t Qi[BB * SQ * DD];
__device__ int8_t Pi[BB * SD * DD];
__device__ int8_t HNi[BB * KH * SD * DD];
__device__ float g_scores[BB][NCOLS];

__device__ __forceinline__ uint32_t smem_u32(const void* p) {
    uint32_t a;
    asm("{ .reg .u64 t; cvta.to.shared.u64 t, %1; cvt.u32.u64 %0, t; }" : "=r"(a) : "l"(p));
    return a;
}

#define CP_ASYNC16(dst, src) \
    asm volatile("cp.async.cg.shared.global [%0], [%1], 16;" :: "r"((uint32_t)(dst)), "l"(src))
#define CP_COMMIT asm volatile("cp.async.commit_group;" ::: "memory")

#define LDSM4(r, a) \
    asm volatile("ldmatrix.sync.aligned.m8n8.x4.shared.b16 {%0,%1,%2,%3}, [%4];" \
        : "=r"((r)[0]), "=r"((r)[1]), "=r"((r)[2]), "=r"((r)[3]) : "r"(a))

#define MMAI8(c, a, b0, b1) \
    asm volatile("mma.sync.aligned.m16n8k32.row.col.s32.s8.s8.s32 " \
        "{%0,%1,%2,%3}, {%4,%5,%6,%7}, {%8,%9}, {%0,%1,%2,%3};" \
        : "+r"((c)[0]), "+r"((c)[1]), "+r"((c)[2]), "+r"((c)[3]) \
        : "r"((a)[0]), "r"((a)[1]), "r"((a)[2]), "r"((a)[3]), "r"(b0), "r"(b1))

// pack int score (|v| < 2^20 guaranteed: <= 128*127*127 scaled dots ~ 5e4) with doc idx
__device__ __forceinline__ uint32_t packmax_i(int v, uint32_t idx) {
    return (((uint32_t)(v + (1 << 20))) << 9) | idx;
}

// ---------------- fused fp32 -> int8 preconvert ----------------
#define N4_Q (BB * SQ * DD / 4)
#define N4_P (BB * SD * DD / 4)
#define N4_HN (BB * KH * SD * DD / 4)
#define N4_TOT (N4_Q + N4_P + N4_HN)

__global__ void cvt_all_kernel(const float4* __restrict__ Q,
                               const float4* __restrict__ P,
                               const float4* __restrict__ HN)
{
    const int i = blockIdx.x * blockDim.x + threadIdx.x;
    if (i >= N4_TOT) return;
    const float4* src; uint32_t* dst; int j;
    if (i < N4_Q)               { src = Q;  dst = (uint32_t*)Qi;  j = i; }
    else if (i < N4_Q + N4_P)   { src = P;  dst = (uint32_t*)Pi;  j = i - N4_Q; }
    else                        { src = HN; dst = (uint32_t*)HNi; j = i - N4_Q - N4_P; }
    const float4 f = src[j];
    int v0 = __float2int_rn(f.x * SCALE_I8);
    int v1 = __float2int_rn(f.y * SCALE_I8);
    int v2 = __float2int_rn(f.z * SCALE_I8);
    int v3 = __float2int_rn(f.w * SCALE_I8);
    v0 = max(-127, min(127, v0));
    v1 = max(-127, min(127, v1));
    v2 = max(-127, min(127, v2));
    v3 = max(-127, min(127, v3));
    dst[j] = (uint32_t)(v0 & 0xFF) | ((uint32_t)(v1 & 0xFF) << 8) |
             ((uint32_t)(v2 & 0xFF) << 16) | ((uint32_t)(v3 & 0xFF) << 24);
}

__device__ __forceinline__ void load_B_chunk(uint32_t dst_base, const int8_t* src, int tid)
{
#pragma unroll
    for (int j = 0; j < 4; ++j) {
        const int it = tid + j * 256;          // 1024 segs: 128 rows x 8 segs of 16B
        const int row = it >> 3, ci = it & 7;
        CP_ASYNC16(dst_base + row * RST + ci * 16, src + row * DD + ci * 16);
    }
}

// ---------------- main kernel (R4 structure, int8 math) ----------------
__global__ __launch_bounds__(256) void maxsim_kernel(
    const float* __restrict__ Q,
    const float* __restrict__ P,
    const float* __restrict__ HN)
{
    extern __shared__ char sm[];
    const uint32_t smb = smem_u32(sm);
    const int tid = threadIdx.x;
    const int wid = tid >> 5;
    const int lid = tid & 31;

    // ---- block -> work mapping ----
    const int8_t* aI; const int8_t* bI;
    const float* aF; const float* bF;
    int qrow0, outcol, validM;
    const int bidx = blockIdx.x;
    if (bidx < 2048) {
        const int mt = bidx >> 6, bp = bidx & 63;
        aI = Qi + (size_t)mt * 128 * DD;  aF = Q + (size_t)mt * 128 * DD;
        bI = Pi + (size_t)bp * SD * DD;   bF = P + (size_t)bp * SD * DD;
        qrow0 = mt * 2; outcol = bp; validM = 128;
    } else {
        const int i = bidx - 2048;
        const int b = i >> 2, k = i & 3;
        aI = Qi + (size_t)b * SQ * DD;    aF = Q + (size_t)b * SQ * DD;
        bI = HNi + (size_t)(b * KH + k) * SD * DD;
        bF = HN + (size_t)(b * KH + k) * SD * DD;
        qrow0 = b; outcol = BB + k; validM = 64;
    }

    // ---- prologue: A (group 0) + B chunks 0,1 ----
#pragma unroll
    for (int j = 0; j < 4; ++j) {
        const int it = tid + j * 256;
        const int row = it >> 3, ci = it & 7;
        if (row < validM)
            CP_ASYNC16(smb + SM_A + row * RST + ci * 16, aI + row * DD + ci * 16);
    }
    if (validM == 64) {  // zero upper A rows for HN blocks (64 rows x 9 uint4)
        for (int j = tid; j < 576; j += 256) {
            const int row = 64 + j / 9, ci = j % 9;
            *(uint4*)(sm + SM_A + row * RST + ci * 16) = make_uint4(0, 0, 0, 0);
        }
    }
    CP_COMMIT;
    load_B_chunk(smb + SM_B, bI, tid);
    CP_COMMIT;
    load_B_chunk(smb + SM_B + BSTG, bI + 128 * DD, tid);
    CP_COMMIT;

    // ---- fragment addressing (b16-view of int8 tiles; layout maps 1:1 to s8 k32 frags) ----
    const int wm = wid >> 2, wn = wid & 3;
    const int m0 = wm * 64, n0 = wn * 32;
    const int a_r = (lid & 7) + ((lid >> 3) & 1) * 8;
    const uint32_t a_c = ((lid >> 4) & 1) * 16;      // k-bytes 0-15 vs 16-31 of 32B chunk
    const uint32_t aBase = smb + SM_A + (uint32_t)((m0 + a_r) * RST) + a_c;
    const int b_r = ((lid >> 4) & 1) * 8 + (lid & 7);
    const uint32_t b_c = ((lid >> 3) & 1) * 16;
    const uint32_t bOff0 = (uint32_t)((n0 + b_r) * RST) + b_c;

    int cfr[4][4][4];
#pragma unroll
    for (int mt = 0; mt < 4; ++mt)
#pragma unroll
        for (int nt = 0; nt < 4; ++nt)
#pragma unroll
            for (int i = 0; i < 4; ++i) cfr[mt][nt][i] = 0;

    uint32_t rmp[4][2];
#pragma unroll
    for (int mt = 0; mt < 4; ++mt) { rmp[mt][0] = 0u; rmp[mt][1] = 0u; }

    // ---- main loop ----
#pragma unroll 1
    for (int ch = 0; ch < NCHUNK; ++ch) {
        if (ch < NCHUNK - 1) asm volatile("cp.async.wait_group 1;" ::: "memory");
        else                 asm volatile("cp.async.wait_group 0;" ::: "memory");
        __syncthreads();

        const uint32_t bb = smb + SM_B + (uint32_t)(ch & 1) * BSTG;
#pragma unroll
        for (int kk = 0; kk < 4; ++kk) {          // 4 x k32 = K128
            const uint32_t ko = kk * 32;          // 32 bytes per k-step
            uint32_t af[4][4], bf2[2][4];
            LDSM4(af[0], aBase + ko);
            LDSM4(af[1], aBase + 16 * RST + ko);
            LDSM4(af[2], aBase + 32 * RST + ko);
            LDSM4(af[3], aBase + 48 * RST + ko);
            LDSM4(bf2[0], bb + bOff0 + ko);
            LDSM4(bf2[1], bb + bOff0 + 16 * RST + ko);
#pragma unroll
            for (int mt = 0; mt < 4; ++mt) {
                MMAI8(cfr[mt][0], af[mt], bf2[0][0], bf2[0][1]);
                MMAI8(cfr[mt][1], af[mt], bf2[0][2], bf2[0][3]);
                MMAI8(cfr[mt][2], af[mt], bf2[1][0], bf2[1][1]);
                MMAI8(cfr[mt][3], af[mt], bf2[1][2], bf2[1][3]);
            }
        }

        // fold into packed (value | doc idx); idx = ch*128 + n0 + nt*8 + 2*(lid&3) + j
        const uint32_t base = (uint32_t)(ch * 128 + n0 + 2 * (lid & 3));
#pragma unroll
        for (int mt = 0; mt < 4; ++mt)
#pragma unroll
            for (int nt = 0; nt < 4; ++nt)
#pragma unroll
                for (int h = 0; h < 2; ++h)
#pragma unroll
                    for (int j = 0; j < 2; ++j) {
                        const uint32_t pk = packmax_i(cfr[mt][nt][h * 2 + j], base + nt * 8 + j);
                        rmp[mt][h] = (pk > rmp[mt][h]) ? pk : rmp[mt][h];
                        cfr[mt][nt][h * 2 + j] = 0;
                    }
        __syncthreads();

        if (ch < NCHUNK - 2) {
            load_B_chunk(smb + SM_B + (uint32_t)(ch & 1) * BSTG,
                         bI + (size_t)(ch + 2) * 128 * DD, tid);
            CP_COMMIT;
        }
    }

    // ---- reduce packed max across lane quads, then across wn ----
    uint32_t* redp = (uint32_t*)(sm + SM_REDP);
#pragma unroll
    for (int mt = 0; mt < 4; ++mt)
#pragma unroll
        for (int h = 0; h < 2; ++h) {
            uint32_t v = rmp[mt][h];
#pragma unroll
            for (int o = 1; o <= 2; o <<= 1) {
                const uint32_t ov = __shfl_xor_sync(0xffffffffu, v, o);
                v = (ov > v) ? ov : v;
            }
            if ((lid & 3) == 0)
                redp[(m0 + mt * 16 + h * 8 + (lid >> 2)) * 4 + wn] = v;
        }
    __syncthreads();

    int* widx = (int*)(sm + SM_WIDX);
    if (tid < 128) {
        uint32_t best = redp[tid * 4];
#pragma unroll
        for (int w = 1; w < 4; ++w) {
            const uint32_t v = redp[tid * 4 + w];
            best = (v > best) ? v : best;
        }
        widx[tid] = (int)(best & 0x1FFu);
    }
    __syncthreads();

    // ---- phase 2: exact fp32 rescore of winners (2 threads per row) ----
    float* exsc = (float*)(sm + SM_EXSC);
    {
        const int r = tid >> 1, hf = tid & 1;
        const int rr = (r < validM) ? r : 0;
        const float* qp = aF + (size_t)rr * DD + hf * 64;
        const float* dp = bF + (size_t)widx[rr] * DD + hf * 64;
        float a0 = 0.f, a1 = 0.f, a2 = 0.f, a3 = 0.f;
#pragma unroll
        for (int j = 0; j < 16; ++j) {
            const float4 qv = __ldg((const float4*)(qp + j * 4));
            const float4 dv = __ldg((const float4*)(dp + j * 4));
            a0 = fmaf(qv.x, dv.x, a0);
            a1 = fmaf(qv.y, dv.y, a1);
            a2 = fmaf(qv.z, dv.z, a2);
            a3 = fmaf(qv.w, dv.w, a3);
        }
        float s = (a0 + a1) + (a2 + a3);
        s += __shfl_xor_sync(0xffffffffu, s, 1);
        if (hf == 0 && r < validM) exsc[r] = s;
    }
    __syncthreads();

    // ---- sum 64 row scores per batch ----
    if (wid < (validM >> 6)) {
        float s = exsc[wid * 64 + lid] + exsc[wid * 64 + 32 + lid];
#pragma unroll
        for (int o = 16; o > 0; o >>= 1) s += __shfl_down_sync(0xffffffffu, s, o);
        if (lid == 0) g_scores[qrow0 + wid][outcol] = s;
    }
}

// ---------------- loss kernel ----------------
__global__ void loss_kernel(float* __restrict__ out)
{
    __shared__ float red[BB];
    const int q = threadIdx.x >> 1, part = threadIdx.x & 1;
    const float* row = &g_scores[q][0];
    const float pos = row[q];

    float m = -INFINITY;
    for (int j = part * 34; j < part * 34 + 34; ++j) m = fmaxf(m, row[j]);
    m = fmaxf(m, __shfl_xor_sync(0xffffffffu, m, 1));
    m = fmaxf(m, pos);

    float sum = (part == 0) ? expf((pos - m) * INV_T) : 0.f;
    for (int j = part * 34; j < part * 34 + 34; ++j) sum += expf((row[j] - m) * INV_T);
    sum += __shfl_xor_sync(0xffffffffu, sum, 1);

    if (part == 0) red[q] = m * INV_T + logf(sum) - pos * INV_T;
    __syncthreads();

    if (threadIdx.x < 32) {
        float s = red[threadIdx.x] + red[threadIdx.x + 32];
#pragma unroll
        for (int o = 16; o > 0; o >>= 1) s += __shfl_down_sync(0xffffffffu, s, o);
        if (threadIdx.x == 0) out[0] = s / (float)BB;
    }
}

extern "C" void kernel_launch(void* const* d_in, const int* in_sizes, int n_in,
                              void* d_out, int out_size)
{
    const float* Q  = (const float*)d_in[0];
    const float* P  = (const float*)d_in[1];
    const float* HN = (const float*)d_in[2];
    (void)in_sizes; (void)n_in; (void)out_size;

    static bool attr_set = false;
    if (!attr_set) {
        cudaFuncSetAttribute(maxsim_kernel,
                             cudaFuncAttributeMaxDynamicSharedMemorySize, SMEM_TOTAL);
        attr_set = true;
    }

    cvt_all_kernel<<<(N4_TOT + 255) / 256, 256>>>(
        (const float4*)Q, (const float4*)P, (const float4*)HN);
    maxsim_kernel<<<2048 + BB * KH, 256, SMEM_TOTAL>>>(Q, P, HN);
    loss_kernel<<<1, 128>>>((float*)d_out);
}